// round 1
// baseline (speedup 1.0000x reference)
#include <cuda_runtime.h>
#include <math.h>

#define M_TOTAL 32768
#define N_TOTAL 640
#define K_TOTAL 512
#define V_VARS  320
#define D_CODE  128

// Scratch (allocation-free: __device__ globals)
__device__ float g_logits[M_TOTAL * N_TOTAL];   // [32768, 640]
__device__ float g_avg[N_TOTAL];                // softmax prob sums per (g,v)

// ---------------------------------------------------------------------------
// f32x2 packed-FP32 helpers (FFMA2 path: 2x fp32 FMA throughput on sm_103a)
// ---------------------------------------------------------------------------
__device__ __forceinline__ unsigned long long dup_f32x2(float x) {
    unsigned long long r;
    asm("mov.b64 %0, {%1, %1};" : "=l"(r) : "f"(x));
    return r;
}
__device__ __forceinline__ unsigned long long pack_f32x2(float x, float y) {
    unsigned long long r;
    asm("mov.b64 %0, {%1, %2};" : "=l"(r) : "f"(x), "f"(y));
    return r;
}
__device__ __forceinline__ void fma_f32x2(unsigned long long& d,
                                          unsigned long long a,
                                          unsigned long long b) {
    asm("fma.rn.f32x2 %0, %1, %2, %0;" : "+l"(d) : "l"(a), "l"(b));
}
__device__ __forceinline__ float2 unpack_f32x2(unsigned long long v) {
    float2 r;
    asm("mov.b64 {%0, %1}, %2;" : "=f"(r.x), "=f"(r.y) : "l"(v));
    return r;
}

// ---------------------------------------------------------------------------
// Accurate fp32 natural log (fdlibm e_logf style, ~1 ulp).
// Immune to --use_fast_math logf degradation; needed because argmax flips
// in the gumbel scores are catastrophic for rel_err.
// Domain here: x in [~6e-8, ~24], always normal, positive, finite.
// ---------------------------------------------------------------------------
__device__ __forceinline__ float log_acc(float x) {
    int ix = __float_as_int(x);
    int e = ((ix >> 23) & 0xff) - 126;
    float m = __int_as_float((ix & 0x007fffff) | 0x3f000000);  // [0.5, 1)
    if (m < 0.70710678118654752f) { m = m + m; e -= 1; }
    float f = m - 1.0f;
    float s = f / (2.0f + f);
    float z = s * s;
    float w = z * z;
    float t1 = w * (0.40000972152f + w * 0.24279078841f);
    float t2 = z * (0.66666662693f + w * 0.28498786688f);
    float R = t2 + t1;
    float hfsq = 0.5f * f * f;
    float dk = (float)e;
    return dk * 0.69313812256f -
           ((hfsq - (s * (hfsq + R) + dk * 9.0580006145e-06f)) - f);
}

// ---------------------------------------------------------------------------
// GEMM: logits = hidden[32768,512] @ w_proj[512,640] + bias
// 128x128 tile, BK=32, 256 threads, 8x8 microtile per thread via FFMA2.
// ---------------------------------------------------------------------------
#define BM 128
#define BN 128
#define BK 32

__global__ void __launch_bounds__(256, 2)
gemm_kernel(const float* __restrict__ A, const float* __restrict__ W,
            const float* __restrict__ bias) {
    __shared__ float As[BK][BM + 4];   // transposed (k-major), +4 pad kills STS conflicts
    __shared__ float Bs[BK][BN];
    const int bm = blockIdx.x * BM;
    const int bn = blockIdx.y * BN;
    const int tid = threadIdx.x;
    const int tr = tid >> 4;           // 0..15 -> rows tr*4..+3 and +64
    const int tc = tid & 15;           // 0..15 -> cols tc*4..+3 and +64

    unsigned long long acc[8][4];
    #pragma unroll
    for (int r = 0; r < 8; r++)
        #pragma unroll
        for (int c = 0; c < 4; c++) acc[r][c] = 0ull;

    for (int k0 = 0; k0 < K_TOTAL; k0 += BK) {
        // A tile: 128 rows x 32 k, stored transposed
        #pragma unroll
        for (int i = 0; i < 4; i++) {
            int idx = tid + i * 256;
            int row = idx >> 3;
            int c4  = idx & 7;
            float4 v = *(const float4*)(A + (size_t)(bm + row) * K_TOTAL + k0 + c4 * 4);
            As[c4 * 4 + 0][row] = v.x;
            As[c4 * 4 + 1][row] = v.y;
            As[c4 * 4 + 2][row] = v.z;
            As[c4 * 4 + 3][row] = v.w;
        }
        // B tile: 32 k x 128 cols
        #pragma unroll
        for (int i = 0; i < 4; i++) {
            int idx = tid + i * 256;
            int kr  = idx >> 5;
            int c4  = idx & 31;
            *(float4*)&Bs[kr][c4 * 4] =
                *(const float4*)(W + (size_t)(k0 + kr) * N_TOTAL + bn + c4 * 4);
        }
        __syncthreads();

        #pragma unroll
        for (int kk = 0; kk < BK; kk++) {
            float4 a0 = *(const float4*)&As[kk][tr * 4];
            float4 a1 = *(const float4*)&As[kk][tr * 4 + 64];
            float4 b0 = *(const float4*)&Bs[kk][tc * 4];
            float4 b1 = *(const float4*)&Bs[kk][tc * 4 + 64];
            unsigned long long bp0 = pack_f32x2(b0.x, b0.y);
            unsigned long long bp1 = pack_f32x2(b0.z, b0.w);
            unsigned long long bp2 = pack_f32x2(b1.x, b1.y);
            unsigned long long bp3 = pack_f32x2(b1.z, b1.w);
            float av[8] = {a0.x, a0.y, a0.z, a0.w, a1.x, a1.y, a1.z, a1.w};
            #pragma unroll
            for (int r = 0; r < 8; r++) {
                unsigned long long ad = dup_f32x2(av[r]);
                fma_f32x2(acc[r][0], ad, bp0);
                fma_f32x2(acc[r][1], ad, bp1);
                fma_f32x2(acc[r][2], ad, bp2);
                fma_f32x2(acc[r][3], ad, bp3);
            }
        }
        __syncthreads();
    }

    // Epilogue: add bias, store
    float bb[8];
    #pragma unroll
    for (int c = 0; c < 4; c++) {
        bb[c]     = bias[bn + tc * 4 + c];
        bb[4 + c] = bias[bn + tc * 4 + 64 + c];
    }
    #pragma unroll
    for (int r = 0; r < 8; r++) {
        int row = bm + tr * 4 + (r < 4 ? r : 60 + r);
        float* cp = g_logits + (size_t)row * N_TOTAL + bn + tc * 4;
        float2 q0 = unpack_f32x2(acc[r][0]);
        float2 q1 = unpack_f32x2(acc[r][1]);
        float2 q2 = unpack_f32x2(acc[r][2]);
        float2 q3 = unpack_f32x2(acc[r][3]);
        float4 o0 = make_float4(q0.x + bb[0], q0.y + bb[1], q1.x + bb[2], q1.y + bb[3]);
        float4 o1 = make_float4(q2.x + bb[4], q2.y + bb[5], q3.x + bb[6], q3.y + bb[7]);
        *(float4*)cp        = o0;
        *(float4*)(cp + 64) = o1;
    }
}

// ---------------------------------------------------------------------------
__global__ void zero_avg_kernel() { g_avg[threadIdx.x] = 0.0f; }

// ---------------------------------------------------------------------------
// Phase 2: per (n,g) row — gumbel argmax -> codevector gather; noise-free
// softmax accumulated into g_avg. One warp per (n,g), 32 rows per warp.
// Grid: 256 blocks x 256 threads = 2048 warps; 2048*32 = 65536 group-rows.
// ---------------------------------------------------------------------------
__global__ void __launch_bounds__(256)
phase2_kernel(const float* __restrict__ gumbel, const float* __restrict__ codevec,
              float* __restrict__ out) {
    __shared__ float s_avg[N_TOTAL];
    const int tid = threadIdx.x;
    for (int i = tid; i < N_TOTAL; i += 256) s_avg[i] = 0.0f;
    __syncthreads();

    const int lane = tid & 31;
    const int warp_global = (blockIdx.x * 256 + tid) >> 5;  // 0..2047
    const int g = warp_global & 1;
    const int nbase = warp_global >> 1;                      // 0..1023

    float acc[10];
    #pragma unroll
    for (int j = 0; j < 10; j++) acc[j] = 0.0f;

    for (int it = 0; it < 32; it++) {
        const int n = nbase + (it << 10);
        const float* lrow = g_logits + (size_t)n * N_TOTAL + g * V_VARS;
        const float* urow = gumbel + (size_t)(n * 2 + g) * V_VARS;

        float l[10];
        float best_s = -3.4e38f;
        int best_i = 0;
        #pragma unroll
        for (int j = 0; j < 10; j++) {
            const int v = lane + (j << 5);
            l[j] = lrow[v];
            const float u = urow[v];
            const float noise = -log_acc(-log_acc(u + 1e-10f) + 1e-10f);
            const float s = l[j] + noise;   // /TAU omitted: monotone, argmax-equal
            if (s > best_s) { best_s = s; best_i = v; }
        }
        // warp argmax (first-index tie-break like jnp.argmax)
        #pragma unroll
        for (int off = 16; off > 0; off >>= 1) {
            const float os = __shfl_xor_sync(0xffffffffu, best_s, off);
            const int   oi = __shfl_xor_sync(0xffffffffu, best_i, off);
            if (os > best_s || (os == best_s && oi < best_i)) { best_s = os; best_i = oi; }
        }

        // noise-free softmax for avg_probs (loose tolerance: __expf OK)
        float lm = l[0];
        #pragma unroll
        for (int j = 1; j < 10; j++) lm = fmaxf(lm, l[j]);
        #pragma unroll
        for (int off = 16; off > 0; off >>= 1)
            lm = fmaxf(lm, __shfl_xor_sync(0xffffffffu, lm, off));
        float e[10];
        float sum = 0.0f;
        #pragma unroll
        for (int j = 0; j < 10; j++) { e[j] = __expf(l[j] - lm); sum += e[j]; }
        #pragma unroll
        for (int off = 16; off > 0; off >>= 1)
            sum += __shfl_xor_sync(0xffffffffu, sum, off);
        const float inv = 1.0f / sum;
        #pragma unroll
        for (int j = 0; j < 10; j++) acc[j] += e[j] * inv;

        // output gather: out[n, g*128 .. +127] = codevectors[g*320 + argmax, :]
        const float4* src = (const float4*)(codevec + (size_t)(g * V_VARS + best_i) * D_CODE);
        float4* dst = (float4*)(out + (size_t)n * 256 + g * D_CODE);
        dst[lane] = src[lane];
    }

    #pragma unroll
    for (int j = 0; j < 10; j++)
        atomicAdd(&s_avg[g * V_VARS + lane + (j << 5)], acc[j]);
    __syncthreads();
    for (int i = tid; i < N_TOTAL; i += 256) atomicAdd(&g_avg[i], s_avg[i]);
}

// ---------------------------------------------------------------------------
// Phase 3: perplexity = sum_g exp(-sum_v avg*log(avg+1e-7)), avg = sum/32768
// ---------------------------------------------------------------------------
__global__ void phase3_kernel(float* __restrict__ dst) {
    __shared__ float hsum[2];
    const int t = threadIdx.x;  // 640 threads
    if (t < 2) hsum[t] = 0.0f;
    __syncthreads();
    const float a = g_avg[t] * (1.0f / 32768.0f);
    float ev = a * log_acc(a + 1e-7f);
    #pragma unroll
    for (int off = 16; off > 0; off >>= 1)
        ev += __shfl_xor_sync(0xffffffffu, ev, off);
    if ((t & 31) == 0) atomicAdd(&hsum[t / 320], ev);
    __syncthreads();
    if (t == 0) dst[0] = expf(-hsum[0]) + expf(-hsum[1]);
}

// ---------------------------------------------------------------------------
extern "C" void kernel_launch(void* const* d_in, const int* in_sizes, int n_in,
                              void* d_out, int out_size) {
    (void)in_sizes; (void)n_in;
    const float* hidden  = (const float*)d_in[0];  // [8,4096,512]
    const float* gumbel  = (const float*)d_in[1];  // [65536,320]
    const float* wproj   = (const float*)d_in[2];  // [512,640]
    const float* bias    = (const float*)d_in[3];  // [640]
    const float* codevec = (const float*)d_in[4];  // [640,128]
    float* out = (float*)d_out;                    // [32768*256] + perplexity

    dim3 grid(M_TOTAL / BM, N_TOTAL / BN);         // 256 x 5
    gemm_kernel<<<grid, 256>>>(hidden, wproj, bias);
    zero_avg_kernel<<<1, 640>>>();
    phase2_kernel<<<256, 256>>>(gumbel, codevec, out);
    phase3_kernel<<<1, 640>>>(out + (out_size - 1));
}

// round 9
// speedup vs baseline: 1.1760x; 1.1760x over previous
#include <cuda_runtime.h>
#include <cuda_bf16.h>
#include <cstdint>
#include <math.h>

#define M_TOTAL 32768
#define N_TOTAL 640
#define K_TOTAL 512
#define V_VARS  320
#define D_CODE  128

// ---------------- device scratch (allocation-free) ----------------
__device__ float g_logits[M_TOTAL * N_TOTAL];          // [32768, 640]
__device__ float g_avg[N_TOTAL];
__device__ __nv_bfloat16 g_A0[M_TOTAL * K_TOTAL];
__device__ __nv_bfloat16 g_A1[M_TOTAL * K_TOTAL];
__device__ __nv_bfloat16 g_A2[M_TOTAL * K_TOTAL];
__device__ __nv_bfloat16 g_B0[N_TOTAL * K_TOTAL];      // [640, 512] (W transposed)
__device__ __nv_bfloat16 g_B1[N_TOTAL * K_TOTAL];
__device__ __nv_bfloat16 g_B2[N_TOTAL * K_TOTAL];

// ---------------- helpers ----------------
__device__ __forceinline__ uint32_t smem_u32(const void* p) {
    uint32_t a;
    asm("{ .reg .u64 t; cvta.to.shared.u64 t, %1; cvt.u32.u64 %0, t; }" : "=r"(a) : "l"(p));
    return a;
}
__device__ __forceinline__ uint32_t swz128(uint32_t off) {
    return off ^ ((off >> 3) & 0x70);
}
__device__ __forceinline__ void cp_async16(uint32_t dst, const void* src) {
    asm volatile("cp.async.cg.shared.global [%0], [%1], 16;" :: "r"(dst), "l"(src));
}
#define CP_COMMIT() asm volatile("cp.async.commit_group;" ::: "memory")
#define CP_WAIT(n)  asm volatile("cp.async.wait_group %0;" :: "n"(n) : "memory")

__device__ __forceinline__ void ldsm_x4(uint32_t& r0, uint32_t& r1, uint32_t& r2,
                                        uint32_t& r3, uint32_t addr) {
    asm volatile("ldmatrix.sync.aligned.m8n8.x4.shared.b16 {%0,%1,%2,%3}, [%4];"
                 : "=r"(r0), "=r"(r1), "=r"(r2), "=r"(r3) : "r"(addr));
}
__device__ __forceinline__ void mma16816(float* d, const uint32_t* a, const uint32_t* b) {
    asm volatile("mma.sync.aligned.m16n8k16.row.col.f32.bf16.bf16.f32 "
                 "{%0,%1,%2,%3}, {%4,%5,%6,%7}, {%8,%9}, {%0,%1,%2,%3};"
                 : "+f"(d[0]), "+f"(d[1]), "+f"(d[2]), "+f"(d[3])
                 : "r"(a[0]), "r"(a[1]), "r"(a[2]), "r"(a[3]), "r"(b[0]), "r"(b[1]));
}

// ---------------------------------------------------------------------------
// Accurate fp32 natural log (fdlibm style, ~1 ulp). Argmax-critical.
// ---------------------------------------------------------------------------
__device__ __forceinline__ float log_acc(float x) {
    int ix = __float_as_int(x);
    int e = ((ix >> 23) & 0xff) - 126;
    float m = __int_as_float((ix & 0x007fffff) | 0x3f000000);
    if (m < 0.70710678118654752f) { m = m + m; e -= 1; }
    float f = m - 1.0f;
    float s = f / (2.0f + f);
    float z = s * s;
    float w = z * z;
    float t1 = w * (0.40000972152f + w * 0.24279078841f);
    float t2 = z * (0.66666662693f + w * 0.28498786688f);
    float R = t2 + t1;
    float hfsq = 0.5f * f * f;
    float dk = (float)e;
    return dk * 0.69313812256f -
           ((hfsq - (s * (hfsq + R) + dk * 9.0580006145e-06f)) - f);
}

// ---------------------------------------------------------------------------
// Split kernels: fp32 -> exact 3-term bf16 decomposition
// ---------------------------------------------------------------------------
__device__ __forceinline__ void split3(float a, __nv_bfloat16& h0,
                                       __nv_bfloat16& h1, __nv_bfloat16& h2) {
    h0 = __float2bfloat16(a);
    float r = a - __bfloat162float(h0);
    h1 = __float2bfloat16(r);
    float r2 = r - __bfloat162float(h1);
    h2 = __float2bfloat16(r2);
}

__global__ void __launch_bounds__(256)
split_a_kernel(const float* __restrict__ A) {
    const size_t i = (size_t)blockIdx.x * 256 + threadIdx.x;   // 8 floats each
    const float4* src = (const float4*)A;
    float4 v0 = src[i * 2], v1 = src[i * 2 + 1];
    float f[8] = {v0.x, v0.y, v0.z, v0.w, v1.x, v1.y, v1.z, v1.w};
    __align__(16) __nv_bfloat16 h0[8], h1[8], h2[8];
    #pragma unroll
    for (int j = 0; j < 8; j++) split3(f[j], h0[j], h1[j], h2[j]);
    ((uint4*)g_A0)[i] = *(const uint4*)h0;
    ((uint4*)g_A1)[i] = *(const uint4*)h1;
    ((uint4*)g_A2)[i] = *(const uint4*)h2;
}

__global__ void __launch_bounds__(512)
split_b_kernel(const float* __restrict__ W) {
    const int n = blockIdx.x;        // 640
    const int k = threadIdx.x;       // 512
    float w = W[(size_t)k * N_TOTAL + n];
    __nv_bfloat16 h0, h1, h2;
    split3(w, h0, h1, h2);
    g_B0[(size_t)n * K_TOTAL + k] = h0;
    g_B1[(size_t)n * K_TOTAL + k] = h1;
    g_B2[(size_t)n * K_TOTAL + k] = h2;
}

// ---------------------------------------------------------------------------
// HMMA GEMM: logits[32768,640] = A @ W + bias via 6-product bf16 split.
// CTA tile 128x128, KC=64, 2-stage cp.async double buffer (6 mats/stage).
// 8 warps (4m x 2n), warp tile 32x64, mma.sync.m16n8k16 bf16->fp32.
// ---------------------------------------------------------------------------
#define KC 64
#define TILE_B (128 * KC * 2)        // 16384 bytes per matrix tile
#define STAGE_B (6 * TILE_B)         // 98304 bytes
#define SMEM_GEMM (2 * STAGE_B)      // 196608 bytes

__global__ void __launch_bounds__(256, 1)
gemm_mma_kernel(const float* __restrict__ bias) {
    extern __shared__ __align__(1024) char smem[];
    const uint32_t sb = smem_u32(smem);
    const int tid = threadIdx.x;
    const int lane = tid & 31;
    const int wid = tid >> 5;
    const int wm = wid & 3;            // 0..3 -> m offset 32*wm
    const int wn = wid >> 2;           // 0..1 -> n offset 64*wn
    const int bid = blockIdx.x;
    const int mt = bid / 5;            // m-major: A tiles L2-resident across 5 N-tiles
    const int nt = bid - mt * 5;
    const int bm = mt * 128;
    const int bn = nt * 128;

    const uint4* gsrc[6] = {
        (const uint4*)g_A0 + (size_t)bm * 64,
        (const uint4*)g_A1 + (size_t)bm * 64,
        (const uint4*)g_A2 + (size_t)bm * 64,
        (const uint4*)g_B0 + (size_t)bn * 64,
        (const uint4*)g_B1 + (size_t)bn * 64,
        (const uint4*)g_B2 + (size_t)bn * 64};

    float acc[16][4];
    #pragma unroll
    for (int i = 0; i < 16; i++)
        #pragma unroll
        for (int j = 0; j < 4; j++) acc[i][j] = 0.0f;

    // ldmatrix source addresses (within-tile offsets, swizzled at use)
    const uint32_t a_row = (uint32_t)(wm * 32 + (lane & 15));
    const uint32_t a_seg = (uint32_t)((lane >> 4) * 16);       // 0 or 16 bytes
    const int bgrp = lane >> 3;                                 // 0..3
    const uint32_t b_row = (uint32_t)(wn * 64 + ((bgrp >> 1) << 3) + (lane & 7));
    const uint32_t b_seg = (uint32_t)((bgrp & 1) * 16);

    auto load_stage = [&](int c, int s) {
        const uint32_t base = sb + (uint32_t)s * STAGE_B;
        #pragma unroll
        for (int mat = 0; mat < 6; mat++) {
            const uint4* src = gsrc[mat];
            const uint32_t d0 = base + mat * TILE_B;
            #pragma unroll
            for (int i = 0; i < 4; i++) {
                const int idx = tid + i * 256;
                const int r = idx >> 3, q = idx & 7;
                cp_async16(d0 + swz128((uint32_t)(r * 128 + q * 16)),
                           src + (size_t)r * 64 + c * 8 + q);
            }
        }
        CP_COMMIT();
    };

    load_stage(0, 0);

    for (int c = 0; c < 8; c++) {
        if (c < 7) { load_stage(c + 1, (c + 1) & 1); CP_WAIT(1); }
        else       { CP_WAIT(0); }
        __syncthreads();

        const uint32_t st = sb + (uint32_t)(c & 1) * STAGE_B;

        #pragma unroll
        for (int kk = 0; kk < 4; kk++) {
            const uint32_t koff = (uint32_t)(kk * 32);      // k-step byte offset in row
            uint32_t b[8][2];
            uint32_t a[2][4];

            // offsets for this warp's ldmatrix rows
            const uint32_t aoff0 = swz128(a_row * 128 + koff + a_seg);
            const uint32_t aoff1 = swz128((a_row + 16) * 128 + koff + a_seg);

            #define LOAD_B(split)                                                   \
                _Pragma("unroll")                                                   \
                for (int np = 0; np < 4; np++) {                                    \
                    uint32_t addr = st + (uint32_t)(3 + (split)) * TILE_B +         \
                        swz128((b_row + np * 16) * 128 + koff + b_seg);             \
                    ldsm_x4(b[2 * np][0], b[2 * np][1], b[2 * np + 1][0],           \
                            b[2 * np + 1][1], addr);                                \
                }
            #define LOAD_A(split)                                                   \
                do {                                                                \
                    uint32_t ab = st + (uint32_t)(split) * TILE_B;                  \
                    ldsm_x4(a[0][0], a[0][1], a[0][2], a[0][3], ab + aoff0);        \
                    ldsm_x4(a[1][0], a[1][1], a[1][2], a[1][3], ab + aoff1);        \
                } while (0)
            #define MMA_ALL()                                                       \
                _Pragma("unroll")                                                   \
                for (int mi = 0; mi < 2; mi++)                                      \
                    _Pragma("unroll")                                               \
                    for (int ni = 0; ni < 8; ni++)                                  \
                        mma16816(acc[mi * 8 + ni], a[mi], b[ni]);

            LOAD_B(0);
            LOAD_A(0); MMA_ALL();      // a0*b0
            LOAD_A(1); MMA_ALL();      // a1*b0
            LOAD_A(2); MMA_ALL();      // a2*b0
            LOAD_B(1);
            LOAD_A(0); MMA_ALL();      // a0*b1
            LOAD_A(1); MMA_ALL();      // a1*b1
            LOAD_B(2);
            LOAD_A(0); MMA_ALL();      // a0*b2

            #undef LOAD_B
            #undef LOAD_A
            #undef MMA_ALL
        }
        __syncthreads();
    }

    // Epilogue: add bias, store fp32 logits
    const int er = bm + wm * 32 + (lane >> 2);
    const int ec = bn + wn * 64 + (lane & 3) * 2;
    #pragma unroll
    for (int ni = 0; ni < 8; ni++) {
        const int col = ec + ni * 8;
        const float b0 = bias[col], b1 = bias[col + 1];
        #pragma unroll
        for (int mi = 0; mi < 2; mi++) {
            const float* c4 = acc[mi * 8 + ni];
            const int row = er + mi * 16;
            float2 v0 = make_float2(c4[0] + b0, c4[1] + b1);
            float2 v1 = make_float2(c4[2] + b0, c4[3] + b1);
            *(float2*)(g_logits + (size_t)row * N_TOTAL + col) = v0;
            *(float2*)(g_logits + (size_t)(row + 8) * N_TOTAL + col) = v1;
        }
    }
}

// ---------------------------------------------------------------------------
__global__ void zero_avg_kernel() { g_avg[threadIdx.x] = 0.0f; }

// ---------------------------------------------------------------------------
// Phase 2: gumbel argmax -> codevector gather; noise-free softmax -> g_avg
// ---------------------------------------------------------------------------
__global__ void __launch_bounds__(256)
phase2_kernel(const float* __restrict__ gumbel, const float* __restrict__ codevec,
              float* __restrict__ out) {
    __shared__ float s_avg[N_TOTAL];
    const int tid = threadIdx.x;
    for (int i = tid; i < N_TOTAL; i += 256) s_avg[i] = 0.0f;
    __syncthreads();

    const int lane = tid & 31;
    const int warp_global = (blockIdx.x * 256 + tid) >> 5;
    const int g = warp_global & 1;
    const int nbase = warp_global >> 1;

    float acc[10];
    #pragma unroll
    for (int j = 0; j < 10; j++) acc[j] = 0.0f;

    for (int it = 0; it < 32; it++) {
        const int n = nbase + (it << 10);
        const float* lrow = g_logits + (size_t)n * N_TOTAL + g * V_VARS;
        const float* urow = gumbel + (size_t)(n * 2 + g) * V_VARS;

        float l[10];
        float best_s = -3.4e38f;
        int best_i = 0;
        #pragma unroll
        for (int j = 0; j < 10; j++) {
            const int v = lane + (j << 5);
            l[j] = lrow[v];
            const float u = urow[v];
            const float noise = -log_acc(-log_acc(u + 1e-10f) + 1e-10f);
            const float s = l[j] + noise;
            if (s > best_s) { best_s = s; best_i = v; }
        }
        #pragma unroll
        for (int off = 16; off > 0; off >>= 1) {
            const float os = __shfl_xor_sync(0xffffffffu, best_s, off);
            const int   oi = __shfl_xor_sync(0xffffffffu, best_i, off);
            if (os > best_s || (os == best_s && oi < best_i)) { best_s = os; best_i = oi; }
        }

        float lm = l[0];
        #pragma unroll
        for (int j = 1; j < 10; j++) lm = fmaxf(lm, l[j]);
        #pragma unroll
        for (int off = 16; off > 0; off >>= 1)
            lm = fmaxf(lm, __shfl_xor_sync(0xffffffffu, lm, off));
        float e[10];
        float sum = 0.0f;
        #pragma unroll
        for (int j = 0; j < 10; j++) { e[j] = __expf(l[j] - lm); sum += e[j]; }
        #pragma unroll
        for (int off = 16; off > 0; off >>= 1)
            sum += __shfl_xor_sync(0xffffffffu, sum, off);
        const float inv = 1.0f / sum;
        #pragma unroll
        for (int j = 0; j < 10; j++) acc[j] += e[j] * inv;

        const float4* srcv = (const float4*)(codevec + (size_t)(g * V_VARS + best_i) * D_CODE);
        float4* dstv = (float4*)(out + (size_t)n * 256 + g * D_CODE);
        dstv[lane] = srcv[lane];
    }

    #pragma unroll
    for (int j = 0; j < 10; j++)
        atomicAdd(&s_avg[g * V_VARS + lane + (j << 5)], acc[j]);
    __syncthreads();
    for (int i = tid; i < N_TOTAL; i += 256) atomicAdd(&g_avg[i], s_avg[i]);
}

// ---------------------------------------------------------------------------
__global__ void phase3_kernel(float* __restrict__ dst) {
    __shared__ float hsum[2];
    const int t = threadIdx.x;  // 640
    if (t < 2) hsum[t] = 0.0f;
    __syncthreads();
    const float a = g_avg[t] * (1.0f / 32768.0f);
    float ev = a * log_acc(a + 1e-7f);
    #pragma unroll
    for (int off = 16; off > 0; off >>= 1)
        ev += __shfl_xor_sync(0xffffffffu, ev, off);
    if ((t & 31) == 0) atomicAdd(&hsum[t / 320], ev);
    __syncthreads();
    if (t == 0) dst[0] = expf(-hsum[0]) + expf(-hsum[1]);
}

// ---------------------------------------------------------------------------
extern "C" void kernel_launch(void* const* d_in, const int* in_sizes, int n_in,
                              void* d_out, int out_size) {
    (void)in_sizes; (void)n_in;
    const float* hidden  = (const float*)d_in[0];  // [8,4096,512]
    const float* gumbel  = (const float*)d_in[1];  // [65536,320]
    const float* wproj   = (const float*)d_in[2];  // [512,640]
    const float* bias    = (const float*)d_in[3];  // [640]
    const float* codevec = (const float*)d_in[4];  // [640,128]
    float* out = (float*)d_out;

    cudaFuncSetAttribute(gemm_mma_kernel,
                         cudaFuncAttributeMaxDynamicSharedMemorySize, SMEM_GEMM);

    split_a_kernel<<<8192, 256>>>(hidden);
    split_b_kernel<<<640, 512>>>(wproj);
    gemm_mma_kernel<<<1280, 256, SMEM_GEMM>>>(bias);
    zero_avg_kernel<<<1, 640>>>();
    phase2_kernel<<<256, 256>>>(gumbel, codevec, out);
    phase3_kernel<<<1, 640>>>(out + (out_size - 1));
}

// round 10
// speedup vs baseline: 1.1836x; 1.0065x over previous
#include <cuda_runtime.h>
#include <cuda_bf16.h>
#include <cstdint>
#include <math.h>

#define M_TOTAL 32768
#define N_TOTAL 640
#define K_TOTAL 512
#define V_VARS  320
#define D_CODE  128

// ---------------- device scratch (allocation-free) ----------------
__device__ float g_logits[M_TOTAL * N_TOTAL];          // [32768, 640]
__device__ float g_avg[N_TOTAL];
__device__ __nv_bfloat16 g_A0[M_TOTAL * K_TOTAL];
__device__ __nv_bfloat16 g_A1[M_TOTAL * K_TOTAL];
__device__ __nv_bfloat16 g_A2[M_TOTAL * K_TOTAL];
__device__ __nv_bfloat16 g_B0[N_TOTAL * K_TOTAL];      // [640, 512] (W transposed)
__device__ __nv_bfloat16 g_B1[N_TOTAL * K_TOTAL];
__device__ __nv_bfloat16 g_B2[N_TOTAL * K_TOTAL];

// ---------------- helpers ----------------
__device__ __forceinline__ uint32_t smem_u32(const void* p) {
    uint32_t a;
    asm("{ .reg .u64 t; cvta.to.shared.u64 t, %1; cvt.u32.u64 %0, t; }" : "=r"(a) : "l"(p));
    return a;
}
__device__ __forceinline__ uint32_t swz128(uint32_t off) {
    return off ^ ((off >> 3) & 0x70);
}
__device__ __forceinline__ void cp_async16(uint32_t dst, const void* src) {
    asm volatile("cp.async.cg.shared.global [%0], [%1], 16;" :: "r"(dst), "l"(src));
}
#define CP_COMMIT() asm volatile("cp.async.commit_group;" ::: "memory")
#define CP_WAIT(n)  asm volatile("cp.async.wait_group %0;" :: "n"(n) : "memory")

__device__ __forceinline__ void ldsm_x4(uint32_t& r0, uint32_t& r1, uint32_t& r2,
                                        uint32_t& r3, uint32_t addr) {
    asm volatile("ldmatrix.sync.aligned.m8n8.x4.shared.b16 {%0,%1,%2,%3}, [%4];"
                 : "=r"(r0), "=r"(r1), "=r"(r2), "=r"(r3) : "r"(addr));
}
__device__ __forceinline__ void mma16816(float* d, const uint32_t* a, const uint32_t* b) {
    asm volatile("mma.sync.aligned.m16n8k16.row.col.f32.bf16.bf16.f32 "
                 "{%0,%1,%2,%3}, {%4,%5,%6,%7}, {%8,%9}, {%0,%1,%2,%3};"
                 : "+f"(d[0]), "+f"(d[1]), "+f"(d[2]), "+f"(d[3])
                 : "r"(a[0]), "r"(a[1]), "r"(a[2]), "r"(a[3]), "r"(b[0]), "r"(b[1]));
}

// ---------------------------------------------------------------------------
// Accurate fp32 natural log (fdlibm style, ~1 ulp). Argmax-critical.
// ---------------------------------------------------------------------------
__device__ __forceinline__ float log_acc(float x) {
    int ix = __float_as_int(x);
    int e = ((ix >> 23) & 0xff) - 126;
    float m = __int_as_float((ix & 0x007fffff) | 0x3f000000);
    if (m < 0.70710678118654752f) { m = m + m; e -= 1; }
    float f = m - 1.0f;
    float s = f / (2.0f + f);
    float z = s * s;
    float w = z * z;
    float t1 = w * (0.40000972152f + w * 0.24279078841f);
    float t2 = z * (0.66666662693f + w * 0.28498786688f);
    float R = t2 + t1;
    float hfsq = 0.5f * f * f;
    float dk = (float)e;
    return dk * 0.69313812256f -
           ((hfsq - (s * (hfsq + R) + dk * 9.0580006145e-06f)) - f);
}

// ---------------------------------------------------------------------------
// Split kernels: fp32 -> exact 3-term bf16 decomposition
// ---------------------------------------------------------------------------
__device__ __forceinline__ void split3(float a, __nv_bfloat16& h0,
                                       __nv_bfloat16& h1, __nv_bfloat16& h2) {
    h0 = __float2bfloat16(a);
    float r = a - __bfloat162float(h0);
    h1 = __float2bfloat16(r);
    float r2 = r - __bfloat162float(h1);
    h2 = __float2bfloat16(r2);
}

__global__ void __launch_bounds__(256)
split_a_kernel(const float* __restrict__ A) {
    const size_t i = (size_t)blockIdx.x * 256 + threadIdx.x;   // 8 floats each
    const float4* src = (const float4*)A;
    float4 v0 = src[i * 2], v1 = src[i * 2 + 1];
    float f[8] = {v0.x, v0.y, v0.z, v0.w, v1.x, v1.y, v1.z, v1.w};
    __align__(16) __nv_bfloat16 h0[8], h1[8], h2[8];
    #pragma unroll
    for (int j = 0; j < 8; j++) split3(f[j], h0[j], h1[j], h2[j]);
    ((uint4*)g_A0)[i] = *(const uint4*)h0;
    ((uint4*)g_A1)[i] = *(const uint4*)h1;
    ((uint4*)g_A2)[i] = *(const uint4*)h2;
}

__global__ void __launch_bounds__(512)
split_b_kernel(const float* __restrict__ W) {
    const int n = blockIdx.x;        // 640
    const int k = threadIdx.x;       // 512
    float w = W[(size_t)k * N_TOTAL + n];
    __nv_bfloat16 h0, h1, h2;
    split3(w, h0, h1, h2);
    g_B0[(size_t)n * K_TOTAL + k] = h0;
    g_B1[(size_t)n * K_TOTAL + k] = h1;
    g_B2[(size_t)n * K_TOTAL + k] = h2;
}

// ---------------------------------------------------------------------------
// HMMA GEMM: logits[32768,640] = A @ W + bias via 6-product bf16 split.
// CTA tile 128x128, KC=32, 2-stage cp.async double buffer, 2 CTAs/SM.
// SMEM: 128B rows hold TWO 32-col matrices side by side (pairs), SW128 swizzle.
//   pair 0: A0 | A1    pair 1: A2 | B2    pair 2: B0 | B1
// 8 warps (4m x 2n), warp tile 32x64, mma.sync.m16n8k16 bf16->fp32.
// ---------------------------------------------------------------------------
#define KC 32
#define TILE_P  16384                // 128 rows x 128B (one pair)
#define STAGE_B (3 * TILE_P)         // 49152 bytes
#define SMEM_GEMM (2 * STAGE_B)      // 98304 bytes -> 2 CTAs/SM

__global__ void __launch_bounds__(256, 2)
gemm_mma_kernel(const float* __restrict__ bias) {
    extern __shared__ __align__(1024) char smem[];
    const uint32_t sb = smem_u32(smem);
    const int tid = threadIdx.x;
    const int lane = tid & 31;
    const int wid = tid >> 5;
    const int wm = wid & 3;            // 0..3 -> m offset 32*wm
    const int wn = wid >> 2;           // 0..1 -> n offset 64*wn
    const int bid = blockIdx.x;
    const int mt = bid / 5;            // m-major: A tiles L2-resident across 5 N-tiles
    const int nt = bid - mt * 5;
    const int bm = mt * 128;
    const int bn = nt * 128;

    // global sources in loader order: A0,A1,A2,B0,B1,B2
    const uint4* gsrc[6] = {
        (const uint4*)g_A0 + (size_t)bm * 64,
        (const uint4*)g_A1 + (size_t)bm * 64,
        (const uint4*)g_A2 + (size_t)bm * 64,
        (const uint4*)g_B0 + (size_t)bn * 64,
        (const uint4*)g_B1 + (size_t)bn * 64,
        (const uint4*)g_B2 + (size_t)bn * 64};
    // destination pair index and half-row byte offset per mat
    const uint32_t pd[6] = {0, 0, 1, 2, 2, 1};
    const uint32_t hd[6] = {0, 64, 0, 0, 64, 64};
    // fragment-source tables per split index
    const uint32_t PAIR_A[3] = {0, 0, 1}, HALF_A[3] = {0, 64, 0};
    const uint32_t PAIR_B[3] = {2, 2, 1}, HALF_B[3] = {0, 64, 64};

    float acc[16][4];
    #pragma unroll
    for (int i = 0; i < 16; i++)
        #pragma unroll
        for (int j = 0; j < 4; j++) acc[i][j] = 0.0f;

    // ldmatrix row/segment decomposition (within-tile, swizzled at use)
    const uint32_t a_row = (uint32_t)(wm * 32 + (lane & 15));
    const uint32_t a_seg = (uint32_t)((lane >> 4) * 16);       // 0 or 16 bytes
    const int bgrp = lane >> 3;                                 // 0..3
    const uint32_t b_row = (uint32_t)(wn * 64 + ((bgrp >> 1) << 3) + (lane & 7));
    const uint32_t b_seg = (uint32_t)((bgrp & 1) * 16);

    auto load_stage = [&](int c, int s) {
        const uint32_t base = sb + (uint32_t)s * STAGE_B;
        #pragma unroll
        for (int mat = 0; mat < 6; mat++) {
            const uint4* src = gsrc[mat];
            const uint32_t d0 = base + pd[mat] * TILE_P;
            const uint32_t h = hd[mat];
            #pragma unroll
            for (int i = 0; i < 2; i++) {
                const int idx = tid + i * 256;          // 0..511
                const int r = idx >> 2, q = idx & 3;    // row, 16B-seg in 64B half
                cp_async16(d0 + swz128((uint32_t)(r * 128 + h + q * 16)),
                           src + (size_t)r * 64 + c * 4 + q);
            }
        }
        CP_COMMIT();
    };

    load_stage(0, 0);

    for (int c = 0; c < 16; c++) {
        if (c < 15) { load_stage(c + 1, (c + 1) & 1); CP_WAIT(1); }
        else        { CP_WAIT(0); }
        __syncthreads();

        const uint32_t st = sb + (uint32_t)(c & 1) * STAGE_B;

        #pragma unroll
        for (int kk = 0; kk < 2; kk++) {
            const uint32_t koff = (uint32_t)(kk * 32);      // k-step byte offset in half-row
            uint32_t b[8][2];
            uint32_t a[2][4];

            #define LOAD_B(split)                                                   \
                _Pragma("unroll")                                                   \
                for (int np = 0; np < 4; np++) {                                    \
                    uint32_t addr = st + PAIR_B[split] * TILE_P +                   \
                        swz128((b_row + np * 16) * 128 + HALF_B[split] + koff + b_seg); \
                    ldsm_x4(b[2 * np][0], b[2 * np][1], b[2 * np + 1][0],           \
                            b[2 * np + 1][1], addr);                                \
                }
            #define LOAD_A(split)                                                   \
                do {                                                                \
                    uint32_t ab = st + PAIR_A[split] * TILE_P;                      \
                    uint32_t hk = HALF_A[split] + koff + a_seg;                     \
                    ldsm_x4(a[0][0], a[0][1], a[0][2], a[0][3],                     \
                            ab + swz128(a_row * 128 + hk));                         \
                    ldsm_x4(a[1][0], a[1][1], a[1][2], a[1][3],                     \
                            ab + swz128((a_row + 16) * 128 + hk));                  \
                } while (0)
            #define MMA_ALL()                                                       \
                _Pragma("unroll")                                                   \
                for (int mi = 0; mi < 2; mi++)                                      \
                    _Pragma("unroll")                                               \
                    for (int ni = 0; ni < 8; ni++)                                  \
                        mma16816(acc[mi * 8 + ni], a[mi], b[ni]);

            LOAD_B(0);
            LOAD_A(0); MMA_ALL();      // a0*b0
            LOAD_A(1); MMA_ALL();      // a1*b0
            LOAD_A(2); MMA_ALL();      // a2*b0
            LOAD_B(1);
            LOAD_A(0); MMA_ALL();      // a0*b1
            LOAD_A(1); MMA_ALL();      // a1*b1
            LOAD_B(2);
            LOAD_A(0); MMA_ALL();      // a0*b2

            #undef LOAD_B
            #undef LOAD_A
            #undef MMA_ALL
        }
        __syncthreads();
    }

    // Epilogue: add bias, store fp32 logits
    const int er = bm + wm * 32 + (lane >> 2);
    const int ec = bn + wn * 64 + (lane & 3) * 2;
    #pragma unroll
    for (int ni = 0; ni < 8; ni++) {
        const int col = ec + ni * 8;
        const float b0 = bias[col], b1 = bias[col + 1];
        #pragma unroll
        for (int mi = 0; mi < 2; mi++) {
            const float* c4 = acc[mi * 8 + ni];
            const int row = er + mi * 16;
            float2 v0 = make_float2(c4[0] + b0, c4[1] + b1);
            float2 v1 = make_float2(c4[2] + b0, c4[3] + b1);
            *(float2*)(g_logits + (size_t)row * N_TOTAL + col) = v0;
            *(float2*)(g_logits + (size_t)(row + 8) * N_TOTAL + col) = v1;
        }
    }
}

// ---------------------------------------------------------------------------
__global__ void zero_avg_kernel() { g_avg[threadIdx.x] = 0.0f; }

// ---------------------------------------------------------------------------
// Phase 2: gumbel argmax -> codevector gather; noise-free softmax -> g_avg
// ---------------------------------------------------------------------------
__global__ void __launch_bounds__(256)
phase2_kernel(const float* __restrict__ gumbel, const float* __restrict__ codevec,
              float* __restrict__ out) {
    __shared__ float s_avg[N_TOTAL];
    const int tid = threadIdx.x;
    for (int i = tid; i < N_TOTAL; i += 256) s_avg[i] = 0.0f;
    __syncthreads();

    const int lane = tid & 31;
    const int warp_global = (blockIdx.x * 256 + tid) >> 5;
    const int g = warp_global & 1;
    const int nbase = warp_global >> 1;

    float acc[10];
    #pragma unroll
    for (int j = 0; j < 10; j++) acc[j] = 0.0f;

    for (int it = 0; it < 32; it++) {
        const int n = nbase + (it << 10);
        const float* lrow = g_logits + (size_t)n * N_TOTAL + g * V_VARS;
        const float* urow = gumbel + (size_t)(n * 2 + g) * V_VARS;

        float l[10];
        float best_s = -3.4e38f;
        int best_i = 0;
        #pragma unroll
        for (int j = 0; j < 10; j++) {
            const int v = lane + (j << 5);
            l[j] = lrow[v];
            const float u = urow[v];
            const float noise = -log_acc(-log_acc(u + 1e-10f) + 1e-10f);
            const float s = l[j] + noise;
            if (s > best_s) { best_s = s; best_i = v; }
        }
        #pragma unroll
        for (int off = 16; off > 0; off >>= 1) {
            const float os = __shfl_xor_sync(0xffffffffu, best_s, off);
            const int   oi = __shfl_xor_sync(0xffffffffu, best_i, off);
            if (os > best_s || (os == best_s && oi < best_i)) { best_s = os; best_i = oi; }
        }

        float lm = l[0];
        #pragma unroll
        for (int j = 1; j < 10; j++) lm = fmaxf(lm, l[j]);
        #pragma unroll
        for (int off = 16; off > 0; off >>= 1)
            lm = fmaxf(lm, __shfl_xor_sync(0xffffffffu, lm, off));
        float e[10];
        float sum = 0.0f;
        #pragma unroll
        for (int j = 0; j < 10; j++) { e[j] = __expf(l[j] - lm); sum += e[j]; }
        #pragma unroll
        for (int off = 16; off > 0; off >>= 1)
            sum += __shfl_xor_sync(0xffffffffu, sum, off);
        const float inv = 1.0f / sum;
        #pragma unroll
        for (int j = 0; j < 10; j++) acc[j] += e[j] * inv;

        const float4* srcv = (const float4*)(codevec + (size_t)(g * V_VARS + best_i) * D_CODE);
        float4* dstv = (float4*)(out + (size_t)n * 256 + g * D_CODE);
        dstv[lane] = srcv[lane];
    }

    #pragma unroll
    for (int j = 0; j < 10; j++)
        atomicAdd(&s_avg[g * V_VARS + lane + (j << 5)], acc[j]);
    __syncthreads();
    for (int i = tid; i < N_TOTAL; i += 256) atomicAdd(&g_avg[i], s_avg[i]);
}

// ---------------------------------------------------------------------------
__global__ void phase3_kernel(float* __restrict__ dst) {
    __shared__ float hsum[2];
    const int t = threadIdx.x;  // 640
    if (t < 2) hsum[t] = 0.0f;
    __syncthreads();
    const float a = g_avg[t] * (1.0f / 32768.0f);
    float ev = a * log_acc(a + 1e-7f);
    #pragma unroll
    for (int off = 16; off > 0; off >>= 1)
        ev += __shfl_xor_sync(0xffffffffu, ev, off);
    if ((t & 31) == 0) atomicAdd(&hsum[t / 320], ev);
    __syncthreads();
    if (t == 0) dst[0] = expf(-hsum[0]) + expf(-hsum[1]);
}

// ---------------------------------------------------------------------------
extern "C" void kernel_launch(void* const* d_in, const int* in_sizes, int n_in,
                              void* d_out, int out_size) {
    (void)in_sizes; (void)n_in;
    const float* hidden  = (const float*)d_in[0];  // [8,4096,512]
    const float* gumbel  = (const float*)d_in[1];  // [65536,320]
    const float* wproj   = (const float*)d_in[2];  // [512,640]
    const float* bias    = (const float*)d_in[3];  // [640]
    const float* codevec = (const float*)d_in[4];  // [640,128]
    float* out = (float*)d_out;

    cudaFuncSetAttribute(gemm_mma_kernel,
                         cudaFuncAttributeMaxDynamicSharedMemorySize, SMEM_GEMM);

    zero_avg_kernel<<<1, 640>>>();
    split_a_kernel<<<8192, 256>>>(hidden);
    split_b_kernel<<<640, 512>>>(wproj);
    gemm_mma_kernel<<<1280, 256, SMEM_GEMM>>>(bias);
    phase2_kernel<<<256, 256>>>(gumbel, codevec, out);
    phase3_kernel<<<1, 640>>>(out + (out_size - 1));
}

// round 11
// speedup vs baseline: 2.0197x; 1.7063x over previous
#include <cuda_runtime.h>
#include <cuda_fp16.h>
#include <cstdint>
#include <math.h>

#define M_TOTAL 32768
#define N_TOTAL 640
#define K_TOTAL 512
#define V_VARS  320
#define D_CODE  128

// ---------------- device scratch (allocation-free) ----------------
__device__ float g_logits[M_TOTAL * N_TOTAL];          // [32768, 640]
__device__ float g_avg[N_TOTAL];
__device__ __half g_A0[M_TOTAL * K_TOTAL];             // A*2^11 split hi
__device__ __half g_A1[M_TOTAL * K_TOTAL];             // A*2^11 split lo
__device__ __half g_B0[N_TOTAL * K_TOTAL];             // (W^T)*2^11 split hi
__device__ __half g_B1[N_TOTAL * K_TOTAL];             // (W^T)*2^11 split lo

// ---------------- helpers ----------------
__device__ __forceinline__ uint32_t smem_u32(const void* p) {
    uint32_t a;
    asm("{ .reg .u64 t; cvta.to.shared.u64 t, %1; cvt.u32.u64 %0, t; }" : "=r"(a) : "l"(p));
    return a;
}
__device__ __forceinline__ uint32_t swz128(uint32_t off) {
    return off ^ ((off >> 3) & 0x70);
}
__device__ __forceinline__ void cp_async16(uint32_t dst, const void* src) {
    asm volatile("cp.async.cg.shared.global [%0], [%1], 16;" :: "r"(dst), "l"(src));
}
#define CP_COMMIT() asm volatile("cp.async.commit_group;" ::: "memory")
#define CP_WAIT(n)  asm volatile("cp.async.wait_group %0;" :: "n"(n) : "memory")

__device__ __forceinline__ void ldsm_x4(uint32_t& r0, uint32_t& r1, uint32_t& r2,
                                        uint32_t& r3, uint32_t addr) {
    asm volatile("ldmatrix.sync.aligned.m8n8.x4.shared.b16 {%0,%1,%2,%3}, [%4];"
                 : "=r"(r0), "=r"(r1), "=r"(r2), "=r"(r3) : "r"(addr));
}
__device__ __forceinline__ void mma16816(float* d, const uint32_t* a, const uint32_t* b) {
    asm volatile("mma.sync.aligned.m16n8k16.row.col.f32.f16.f16.f32 "
                 "{%0,%1,%2,%3}, {%4,%5,%6,%7}, {%8,%9}, {%0,%1,%2,%3};"
                 : "+f"(d[0]), "+f"(d[1]), "+f"(d[2]), "+f"(d[3])
                 : "r"(a[0]), "r"(a[1]), "r"(a[2]), "r"(a[3]), "r"(b[0]), "r"(b[1]));
}

// ---------------------------------------------------------------------------
// Accurate fp32 natural log (fdlibm style, ~1 ulp). Argmax-critical.
// ---------------------------------------------------------------------------
__device__ __forceinline__ float log_acc(float x) {
    int ix = __float_as_int(x);
    int e = ((ix >> 23) & 0xff) - 126;
    float m = __int_as_float((ix & 0x007fffff) | 0x3f000000);
    if (m < 0.70710678118654752f) { m = m + m; e -= 1; }
    float f = m - 1.0f;
    float s = f / (2.0f + f);
    float z = s * s;
    float w = z * z;
    float t1 = w * (0.40000972152f + w * 0.24279078841f);
    float t2 = z * (0.66666662693f + w * 0.28498786688f);
    float R = t2 + t1;
    float hfsq = 0.5f * f * f;
    float dk = (float)e;
    return dk * 0.69313812256f -
           ((hfsq - (s * (hfsq + R) + dk * 9.0580006145e-06f)) - f);
}

// ---------------------------------------------------------------------------
// Split: fp32 -> 2-term fp16 decomposition of (x * 2^11). Residual <= 2^-22|x|.
// ---------------------------------------------------------------------------
__device__ __forceinline__ void split2h(float x, __half& h0, __half& h1) {
    float s = x * 2048.0f;
    h0 = __float2half_rn(s);
    float r = s - __half2float(h0);
    h1 = __float2half_rn(r);
}

__global__ void __launch_bounds__(256)
split_a_kernel(const float* __restrict__ A) {
    const size_t i = (size_t)blockIdx.x * 256 + threadIdx.x;   // 8 floats each
    const float4* src = (const float4*)A;
    float4 v0 = src[i * 2], v1 = src[i * 2 + 1];
    float f[8] = {v0.x, v0.y, v0.z, v0.w, v1.x, v1.y, v1.z, v1.w};
    __align__(16) __half h0[8], h1[8];
    #pragma unroll
    for (int j = 0; j < 8; j++) split2h(f[j], h0[j], h1[j]);
    ((uint4*)g_A0)[i] = *(const uint4*)h0;
    ((uint4*)g_A1)[i] = *(const uint4*)h1;
}

__global__ void __launch_bounds__(512)
split_b_kernel(const float* __restrict__ W) {
    const int n = blockIdx.x;        // 640
    const int k = threadIdx.x;       // 512
    float w = W[(size_t)k * N_TOTAL + n];
    __half h0, h1;
    split2h(w, h0, h1);
    g_B0[(size_t)n * K_TOTAL + k] = h0;
    g_B1[(size_t)n * K_TOTAL + k] = h1;
}

// ---------------------------------------------------------------------------
// HMMA GEMM: logits = (A @ W) + bias via 3-product fp16 2-term split
//   (a0b0 + a1b0 + a0b1; operands pre-scaled by 2^11, result scaled 2^-22).
// CTA tile 128x128, KC=32, 2-stage cp.async double buffer, 2 CTAs/SM.
// SMEM: 128B rows hold TWO 32-col matrices side by side, SW128 swizzle.
//   pair 0: A0 | A1    pair 1: B0 | B1
// 8 warps (4m x 2n), warp tile 32x64, mma.sync.m16n8k16 f16->fp32.
// ---------------------------------------------------------------------------
#define KC 32
#define TILE_P  16384                // 128 rows x 128B (one pair)
#define STAGE_B (2 * TILE_P)         // 32768 bytes
#define SMEM_GEMM (2 * STAGE_B)      // 65536 bytes -> 2 CTAs/SM

__global__ void __launch_bounds__(256, 2)
gemm_mma_kernel(const float* __restrict__ bias) {
    extern __shared__ __align__(1024) char smem[];
    const uint32_t sb = smem_u32(smem);
    const int tid = threadIdx.x;
    const int lane = tid & 31;
    const int wid = tid >> 5;
    const int wm = wid & 3;            // 0..3 -> m offset 32*wm
    const int wn = wid >> 2;           // 0..1 -> n offset 64*wn
    const int bid = blockIdx.x;
    const int mt = bid / 5;            // m-major: A tiles L2-resident across 5 N-tiles
    const int nt = bid - mt * 5;
    const int bm = mt * 128;
    const int bn = nt * 128;

    // global sources: A0,A1 -> pair0 halves 0/64; B0,B1 -> pair1 halves 0/64
    const uint4* gsrc[4] = {
        (const uint4*)g_A0 + (size_t)bm * 64,
        (const uint4*)g_A1 + (size_t)bm * 64,
        (const uint4*)g_B0 + (size_t)bn * 64,
        (const uint4*)g_B1 + (size_t)bn * 64};
    const uint32_t pd[4] = {0, 0, 1, 1};
    const uint32_t hd[4] = {0, 64, 0, 64};

    float acc[16][4];
    #pragma unroll
    for (int i = 0; i < 16; i++)
        #pragma unroll
        for (int j = 0; j < 4; j++) acc[i][j] = 0.0f;

    // ldmatrix row/segment decomposition (within-tile, swizzled at use)
    const uint32_t a_row = (uint32_t)(wm * 32 + (lane & 15));
    const uint32_t a_seg = (uint32_t)((lane >> 4) * 16);       // 0 or 16 bytes
    const int bgrp = lane >> 3;                                 // 0..3
    const uint32_t b_row = (uint32_t)(wn * 64 + ((bgrp >> 1) << 3) + (lane & 7));
    const uint32_t b_seg = (uint32_t)((bgrp & 1) * 16);

    auto load_stage = [&](int c, int s) {
        const uint32_t base = sb + (uint32_t)s * STAGE_B;
        #pragma unroll
        for (int mat = 0; mat < 4; mat++) {
            const uint4* src = gsrc[mat];
            const uint32_t d0 = base + pd[mat] * TILE_P;
            const uint32_t h = hd[mat];
            #pragma unroll
            for (int i = 0; i < 2; i++) {
                const int idx = tid + i * 256;          // 0..511
                const int r = idx >> 2, q = idx & 3;    // row, 16B-seg in 64B half
                cp_async16(d0 + swz128((uint32_t)(r * 128 + h + q * 16)),
                           src + (size_t)r * 64 + c * 4 + q);
            }
        }
        CP_COMMIT();
    };

    load_stage(0, 0);

    for (int c = 0; c < 16; c++) {
        if (c < 15) { load_stage(c + 1, (c + 1) & 1); CP_WAIT(1); }
        else        { CP_WAIT(0); }
        __syncthreads();

        const uint32_t st = sb + (uint32_t)(c & 1) * STAGE_B;

        #pragma unroll
        for (int kk = 0; kk < 2; kk++) {
            const uint32_t koff = (uint32_t)(kk * 32);      // k-step byte offset in half-row
            uint32_t b[8][2];
            uint32_t a0r[2][4], a1r[2][4];

            #define LOAD_B(half)                                                    \
                _Pragma("unroll")                                                   \
                for (int np = 0; np < 4; np++) {                                    \
                    uint32_t addr = st + 1 * TILE_P +                               \
                        swz128((b_row + np * 16) * 128 + (half) + koff + b_seg);    \
                    ldsm_x4(b[2 * np][0], b[2 * np][1], b[2 * np + 1][0],           \
                            b[2 * np + 1][1], addr);                                \
                }
            #define LOAD_A(ar, half)                                                \
                do {                                                                \
                    uint32_t hk = (half) + koff + a_seg;                            \
                    ldsm_x4((ar)[0][0], (ar)[0][1], (ar)[0][2], (ar)[0][3],         \
                            st + swz128(a_row * 128 + hk));                         \
                    ldsm_x4((ar)[1][0], (ar)[1][1], (ar)[1][2], (ar)[1][3],         \
                            st + swz128((a_row + 16) * 128 + hk));                  \
                } while (0)
            #define MMA_ALL(ar)                                                     \
                _Pragma("unroll")                                                   \
                for (int mi = 0; mi < 2; mi++)                                      \
                    _Pragma("unroll")                                               \
                    for (int ni = 0; ni < 8; ni++)                                  \
                        mma16816(acc[mi * 8 + ni], (ar)[mi], b[ni]);

            LOAD_B(0);                 // B0
            LOAD_A(a0r, 0);            // A0
            MMA_ALL(a0r);              // a0*b0
            LOAD_A(a1r, 64);           // A1
            MMA_ALL(a1r);              // a1*b0
            LOAD_B(64);                // B1 (reuse b regs)
            MMA_ALL(a0r);              // a0*b1

            #undef LOAD_B
            #undef LOAD_A
            #undef MMA_ALL
        }
        __syncthreads();
    }

    // Epilogue: descale by 2^-22, add bias, store fp32 logits
    const float DS = 1.0f / 4194304.0f;   // 2^-22
    const int er = bm + wm * 32 + (lane >> 2);
    const int ec = bn + wn * 64 + (lane & 3) * 2;
    #pragma unroll
    for (int ni = 0; ni < 8; ni++) {
        const int col = ec + ni * 8;
        const float b0 = bias[col], b1 = bias[col + 1];
        #pragma unroll
        for (int mi = 0; mi < 2; mi++) {
            const float* c4 = acc[mi * 8 + ni];
            const int row = er + mi * 16;
            float2 v0 = make_float2(c4[0] * DS + b0, c4[1] * DS + b1);
            float2 v1 = make_float2(c4[2] * DS + b0, c4[3] * DS + b1);
            *(float2*)(g_logits + (size_t)row * N_TOTAL + col) = v0;
            *(float2*)(g_logits + (size_t)(row + 8) * N_TOTAL + col) = v1;
        }
    }
}

// ---------------------------------------------------------------------------
__global__ void zero_avg_kernel() { g_avg[threadIdx.x] = 0.0f; }

// ---------------------------------------------------------------------------
// Phase 2: gumbel argmax -> codevector gather; noise-free softmax -> g_avg
// 2048 blocks x 8 warps; each warp handles 4 (n,g) rows -> ~48 warps/SM.
// ---------------------------------------------------------------------------
__global__ void __launch_bounds__(256)
phase2_kernel(const float* __restrict__ gumbel, const float* __restrict__ codevec,
              float* __restrict__ out) {
    __shared__ float s_avg[N_TOTAL];
    const int tid = threadIdx.x;
    for (int i = tid; i < N_TOTAL; i += 256) s_avg[i] = 0.0f;
    __syncthreads();

    const int lane = tid & 31;
    const int warp_global = (blockIdx.x * 256 + tid) >> 5;   // 0..16383
    const int g = warp_global & 1;
    const int nbase = warp_global >> 1;                       // 0..8191

    float acc[10];
    #pragma unroll
    for (int j = 0; j < 10; j++) acc[j] = 0.0f;

    for (int it = 0; it < 4; it++) {
        const int n = nbase + (it << 13);                     // + it*8192
        const float* lrow = g_logits + (size_t)n * N_TOTAL + g * V_VARS;
        const float* urow = gumbel + (size_t)(n * 2 + g) * V_VARS;

        float l[10];
        float best_s = -3.4e38f;
        int best_i = 0;
        #pragma unroll
        for (int j = 0; j < 10; j++) {
            const int v = lane + (j << 5);
            l[j] = lrow[v];
            const float u = urow[v];
            const float noise = -log_acc(-log_acc(u + 1e-10f) + 1e-10f);
            const float s = l[j] + noise;
            if (s > best_s) { best_s = s; best_i = v; }
        }
        #pragma unroll
        for (int off = 16; off > 0; off >>= 1) {
            const float os = __shfl_xor_sync(0xffffffffu, best_s, off);
            const int   oi = __shfl_xor_sync(0xffffffffu, best_i, off);
            if (os > best_s || (os == best_s && oi < best_i)) { best_s = os; best_i = oi; }
        }

        float lm = l[0];
        #pragma unroll
        for (int j = 1; j < 10; j++) lm = fmaxf(lm, l[j]);
        #pragma unroll
        for (int off = 16; off > 0; off >>= 1)
            lm = fmaxf(lm, __shfl_xor_sync(0xffffffffu, lm, off));
        float e[10];
        float sum = 0.0f;
        #pragma unroll
        for (int j = 0; j < 10; j++) { e[j] = __expf(l[j] - lm); sum += e[j]; }
        #pragma unroll
        for (int off = 16; off > 0; off >>= 1)
            sum += __shfl_xor_sync(0xffffffffu, sum, off);
        const float inv = 1.0f / sum;
        #pragma unroll
        for (int j = 0; j < 10; j++) acc[j] += e[j] * inv;

        const float4* srcv = (const float4*)(codevec + (size_t)(g * V_VARS + best_i) * D_CODE);
        float4* dstv = (float4*)(out + (size_t)n * 256 + g * D_CODE);
        dstv[lane] = srcv[lane];
    }

    #pragma unroll
    for (int j = 0; j < 10; j++)
        atomicAdd(&s_avg[g * V_VARS + lane + (j << 5)], acc[j]);
    __syncthreads();
    for (int i = tid; i < N_TOTAL; i += 256) atomicAdd(&g_avg[i], s_avg[i]);
}

// ---------------------------------------------------------------------------
__global__ void phase3_kernel(float* __restrict__ dst) {
    __shared__ float hsum[2];
    const int t = threadIdx.x;  // 640
    if (t < 2) hsum[t] = 0.0f;
    __syncthreads();
    const float a = g_avg[t] * (1.0f / 32768.0f);
    float ev = a * log_acc(a + 1e-7f);
    #pragma unroll
    for (int off = 16; off > 0; off >>= 1)
        ev += __shfl_xor_sync(0xffffffffu, ev, off);
    if ((t & 31) == 0) atomicAdd(&hsum[t / 320], ev);
    __syncthreads();
    if (t == 0) dst[0] = expf(-hsum[0]) + expf(-hsum[1]);
}

// ---------------------------------------------------------------------------
extern "C" void kernel_launch(void* const* d_in, const int* in_sizes, int n_in,
                              void* d_out, int out_size) {
    (void)in_sizes; (void)n_in;
    const float* hidden  = (const float*)d_in[0];  // [8,4096,512]
    const float* gumbel  = (const float*)d_in[1];  // [65536,320]
    const float* wproj   = (const float*)d_in[2];  // [512,640]
    const float* bias    = (const float*)d_in[3];  // [640]
    const float* codevec = (const float*)d_in[4];  // [640,128]
    float* out = (float*)d_out;

    cudaFuncSetAttribute(gemm_mma_kernel,
                         cudaFuncAttributeMaxDynamicSharedMemorySize, SMEM_GEMM);

    zero_avg_kernel<<<1, 640>>>();
    split_a_kernel<<<8192, 256>>>(hidden);
    split_b_kernel<<<640, 512>>>(wproj);
    gemm_mma_kernel<<<1280, 256, SMEM_GEMM>>>(bias);
    phase2_kernel<<<2048, 256>>>(gumbel, codevec, out);
    phase3_kernel<<<1, 640>>>(out + (out_size - 1));
}

// round 14
// speedup vs baseline: 2.6316x; 1.3030x over previous
#include <cuda_runtime.h>
#include <cuda_fp16.h>
#include <cstdint>
#include <math.h>

#define M_TOTAL 32768
#define N_TOTAL 640
#define K_TOTAL 512
#define V_VARS  320
#define D_CODE  128

// ---------------- device scratch (allocation-free) ----------------
__device__ float g_logits[M_TOTAL * N_TOTAL];          // [32768, 640]
__device__ float g_avg[N_TOTAL];
__device__ __half g_A0[M_TOTAL * K_TOTAL];             // A*2^11 split hi
__device__ __half g_A1[M_TOTAL * K_TOTAL];             // A*2^11 split lo
__device__ __half g_B0[N_TOTAL * K_TOTAL];             // (W^T)*2^11 split hi
__device__ __half g_B1[N_TOTAL * K_TOTAL];             // (W^T)*2^11 split lo

// ---------------- helpers ----------------
__device__ __forceinline__ uint32_t smem_u32(const void* p) {
    uint32_t a;
    asm("{ .reg .u64 t; cvta.to.shared.u64 t, %1; cvt.u32.u64 %0, t; }" : "=r"(a) : "l"(p));
    return a;
}
__device__ __forceinline__ uint32_t swz128(uint32_t off) {
    return off ^ ((off >> 3) & 0x70);
}
__device__ __forceinline__ void cp_async16(uint32_t dst, const void* src) {
    asm volatile("cp.async.cg.shared.global [%0], [%1], 16;" :: "r"(dst), "l"(src));
}
#define CP_COMMIT() asm volatile("cp.async.commit_group;" ::: "memory")
#define CP_WAIT(n)  asm volatile("cp.async.wait_group %0;" :: "n"(n) : "memory")

__device__ __forceinline__ void ldsm_x4(uint32_t& r0, uint32_t& r1, uint32_t& r2,
                                        uint32_t& r3, uint32_t addr) {
    asm volatile("ldmatrix.sync.aligned.m8n8.x4.shared.b16 {%0,%1,%2,%3}, [%4];"
                 : "=r"(r0), "=r"(r1), "=r"(r2), "=r"(r3) : "r"(addr));
}
__device__ __forceinline__ void mma16816(float* d, const uint32_t* a, const uint32_t* b) {
    asm volatile("mma.sync.aligned.m16n8k16.row.col.f32.f16.f16.f32 "
                 "{%0,%1,%2,%3}, {%4,%5,%6,%7}, {%8,%9}, {%0,%1,%2,%3};"
                 : "+f"(d[0]), "+f"(d[1]), "+f"(d[2]), "+f"(d[3])
                 : "r"(a[0]), "r"(a[1]), "r"(a[2]), "r"(a[3]), "r"(b[0]), "r"(b[1]));
}

// ---------------------------------------------------------------------------
// Accurate fp32 natural log (fdlibm style, ~1 ulp). Refine-path only.
// ---------------------------------------------------------------------------
__device__ __forceinline__ float log_acc(float x) {
    int ix = __float_as_int(x);
    int e = ((ix >> 23) & 0xff) - 126;
    float m = __int_as_float((ix & 0x007fffff) | 0x3f000000);
    if (m < 0.70710678118654752f) { m = m + m; e -= 1; }
    float f = m - 1.0f;
    float s = f / (2.0f + f);
    float z = s * s;
    float w = z * z;
    float t1 = w * (0.40000972152f + w * 0.24279078841f);
    float t2 = z * (0.66666662693f + w * 0.28498786688f);
    float R = t2 + t1;
    float hfsq = 0.5f * f * f;
    float dk = (float)e;
    return dk * 0.69313812256f -
           ((hfsq - (s * (hfsq + R) + dk * 9.0580006145e-06f)) - f);
}

// ---------------------------------------------------------------------------
// Split: fp32 -> 2-term fp16 decomposition of (x * 2^11). Residual <= 2^-22|x|.
// ---------------------------------------------------------------------------
__device__ __forceinline__ void split2h(float x, __half& h0, __half& h1) {
    float s = x * 2048.0f;
    h0 = __float2half_rn(s);
    float r = s - __half2float(h0);
    h1 = __float2half_rn(r);
}

__global__ void __launch_bounds__(256)
split_a_kernel(const float* __restrict__ A) {
    if (blockIdx.x == 0) {   // fold g_avg zeroing in (any pre-phase2 kernel works)
        for (int i = threadIdx.x; i < N_TOTAL; i += 256) g_avg[i] = 0.0f;
    }
    const size_t i = (size_t)blockIdx.x * 256 + threadIdx.x;   // 8 floats each
    const float4* src = (const float4*)A;
    float4 v0 = src[i * 2], v1 = src[i * 2 + 1];
    float f[8] = {v0.x, v0.y, v0.z, v0.w, v1.x, v1.y, v1.z, v1.w};
    __align__(16) __half h0[8], h1[8];
    #pragma unroll
    for (int j = 0; j < 8; j++) split2h(f[j], h0[j], h1[j]);
    ((uint4*)g_A0)[i] = *(const uint4*)h0;
    ((uint4*)g_A1)[i] = *(const uint4*)h1;
}

__global__ void __launch_bounds__(512)
split_b_kernel(const float* __restrict__ W) {
    const int n = blockIdx.x;        // 640
    const int k = threadIdx.x;       // 512
    float w = W[(size_t)k * N_TOTAL + n];
    __half h0, h1;
    split2h(w, h0, h1);
    g_B0[(size_t)n * K_TOTAL + k] = h0;
    g_B1[(size_t)n * K_TOTAL + k] = h1;
}

// ---------------------------------------------------------------------------
// HMMA GEMM: logits = (A @ W) + bias via 3-product fp16 2-term split.
// CTA tile 128x128, KC=32, 2-stage cp.async double buffer, 2 CTAs/SM.
// (SMEM-bandwidth-bound at ~92% of the 128B/cyc crossbar -> at roofline.)
// ---------------------------------------------------------------------------
#define KC 32
#define TILE_P  16384                // 128 rows x 128B (one pair)
#define STAGE_B (2 * TILE_P)         // 32768 bytes
#define SMEM_GEMM (2 * STAGE_B)      // 65536 bytes -> 2 CTAs/SM

__global__ void __launch_bounds__(256, 2)
gemm_mma_kernel(const float* __restrict__ bias) {
    extern __shared__ __align__(1024) char smem[];
    const uint32_t sb = smem_u32(smem);
    const int tid = threadIdx.x;
    const int lane = tid & 31;
    const int wid = tid >> 5;
    const int wm = wid & 3;            // 0..3 -> m offset 32*wm
    const int wn = wid >> 2;           // 0..1 -> n offset 64*wn
    const int bid = blockIdx.x;
    const int mt = bid / 5;            // m-major: A tiles L2-resident across 5 N-tiles
    const int nt = bid - mt * 5;
    const int bm = mt * 128;
    const int bn = nt * 128;

    const uint4* gsrc[4] = {
        (const uint4*)g_A0 + (size_t)bm * 64,
        (const uint4*)g_A1 + (size_t)bm * 64,
        (const uint4*)g_B0 + (size_t)bn * 64,
        (const uint4*)g_B1 + (size_t)bn * 64};
    const uint32_t pd[4] = {0, 0, 1, 1};
    const uint32_t hd[4] = {0, 64, 0, 64};

    float acc[16][4];
    #pragma unroll
    for (int i = 0; i < 16; i++)
        #pragma unroll
        for (int j = 0; j < 4; j++) acc[i][j] = 0.0f;

    const uint32_t a_row = (uint32_t)(wm * 32 + (lane & 15));
    const uint32_t a_seg = (uint32_t)((lane >> 4) * 16);       // 0 or 16 bytes
    const int bgrp = lane >> 3;                                 // 0..3
    const uint32_t b_row = (uint32_t)(wn * 64 + ((bgrp >> 1) << 3) + (lane & 7));
    const uint32_t b_seg = (uint32_t)((bgrp & 1) * 16);

    auto load_stage = [&](int c, int s) {
        const uint32_t base = sb + (uint32_t)s * STAGE_B;
        #pragma unroll
        for (int mat = 0; mat < 4; mat++) {
            const uint4* src = gsrc[mat];
            const uint32_t d0 = base + pd[mat] * TILE_P;
            const uint32_t h = hd[mat];
            #pragma unroll
            for (int i = 0; i < 2; i++) {
                const int idx = tid + i * 256;          // 0..511
                const int r = idx >> 2, q = idx & 3;    // row, 16B-seg in 64B half
                cp_async16(d0 + swz128((uint32_t)(r * 128 + h + q * 16)),
                           src + (size_t)r * 64 + c * 4 + q);
            }
        }
        CP_COMMIT();
    };

    load_stage(0, 0);

    for (int c = 0; c < 16; c++) {
        if (c < 15) { load_stage(c + 1, (c + 1) & 1); CP_WAIT(1); }
        else        { CP_WAIT(0); }
        __syncthreads();

        const uint32_t st = sb + (uint32_t)(c & 1) * STAGE_B;

        #pragma unroll
        for (int kk = 0; kk < 2; kk++) {
            const uint32_t koff = (uint32_t)(kk * 32);
            uint32_t b[8][2];
            uint32_t a0r[2][4], a1r[2][4];

            #define LOAD_B(half)                                                    \
                _Pragma("unroll")                                                   \
                for (int np = 0; np < 4; np++) {                                    \
                    uint32_t addr = st + 1 * TILE_P +                               \
                        swz128((b_row + np * 16) * 128 + (half) + koff + b_seg);    \
                    ldsm_x4(b[2 * np][0], b[2 * np][1], b[2 * np + 1][0],           \
                            b[2 * np + 1][1], addr);                                \
                }
            #define LOAD_A(ar, half)                                                \
                do {                                                                \
                    uint32_t hk = (half) + koff + a_seg;                            \
                    ldsm_x4((ar)[0][0], (ar)[0][1], (ar)[0][2], (ar)[0][3],         \
                            st + swz128(a_row * 128 + hk));                         \
                    ldsm_x4((ar)[1][0], (ar)[1][1], (ar)[1][2], (ar)[1][3],         \
                            st + swz128((a_row + 16) * 128 + hk));                  \
                } while (0)
            #define MMA_ALL(ar)                                                     \
                _Pragma("unroll")                                                   \
                for (int mi = 0; mi < 2; mi++)                                      \
                    _Pragma("unroll")                                               \
                    for (int ni = 0; ni < 8; ni++)                                  \
                        mma16816(acc[mi * 8 + ni], (ar)[mi], b[ni]);

            LOAD_B(0);                 // B0
            LOAD_A(a0r, 0);            // A0
            MMA_ALL(a0r);              // a0*b0
            LOAD_A(a1r, 64);           // A1
            MMA_ALL(a1r);              // a1*b0
            LOAD_B(64);                // B1 (reuse b regs)
            MMA_ALL(a0r);              // a0*b1

            #undef LOAD_B
            #undef LOAD_A
            #undef MMA_ALL
        }
        __syncthreads();
    }

    // Epilogue: descale by 2^-22, add bias, store fp32 logits
    const float DS = 1.0f / 4194304.0f;   // 2^-22
    const int er = bm + wm * 32 + (lane >> 2);
    const int ec = bn + wn * 64 + (lane & 3) * 2;
    #pragma unroll
    for (int ni = 0; ni < 8; ni++) {
        const int col = ec + ni * 8;
        const float b0 = bias[col], b1 = bias[col + 1];
        #pragma unroll
        for (int mi = 0; mi < 2; mi++) {
            const float* c4 = acc[mi * 8 + ni];
            const int row = er + mi * 16;
            float2 v0 = make_float2(c4[0] * DS + b0, c4[1] * DS + b1);
            float2 v1 = make_float2(c4[2] * DS + b0, c4[3] * DS + b1);
            *(float2*)(g_logits + (size_t)row * N_TOTAL + col) = v0;
            *(float2*)(g_logits + (size_t)(row + 8) * N_TOTAL + col) = v1;
        }
    }
}

// ---------------------------------------------------------------------------
// Phase 2: gumbel argmax (fast __logf scoring + exact refine when warp top-2
// gap < 1e-2; coarse error amplifies as 1.2e-7/w for winners with small
// w=-log(u), so the wide guard is required) -> codevector gather; noise-free
// softmax -> g_avg. 2048 blocks x 8 warps, 4 rows per warp.
// ---------------------------------------------------------------------------
__global__ void __launch_bounds__(256)
phase2_kernel(const float* __restrict__ gumbel, const float* __restrict__ codevec,
              float* __restrict__ out) {
    __shared__ float s_avg[N_TOTAL];
    const int tid = threadIdx.x;
    for (int i = tid; i < N_TOTAL; i += 256) s_avg[i] = 0.0f;
    __syncthreads();

    const int lane = tid & 31;
    const int warp_global = (blockIdx.x * 256 + tid) >> 5;   // 0..16383
    const int g = warp_global & 1;
    const int nbase = warp_global >> 1;                       // 0..8191

    float acc[10];
    #pragma unroll
    for (int j = 0; j < 10; j++) acc[j] = 0.0f;

    for (int it = 0; it < 4; it++) {
        const int n = nbase + (it << 13);                     // + it*8192
        const float* lrow = g_logits + (size_t)n * N_TOTAL + g * V_VARS;
        const float* urow = gumbel + (size_t)(n * 2 + g) * V_VARS;

        float l[10];
        float s1 = -3.4e38f, s2 = -3.4e38f;
        int i1 = 0;
        #pragma unroll
        for (int j = 0; j < 10; j++) {
            const int v = lane + (j << 5);
            l[j] = lrow[v];
            const float u = urow[v];
            const float noise = -__logf(-__logf(u + 1e-10f) + 1e-10f);
            const float s = l[j] + noise;
            if (s > s1) { s2 = s1; s1 = s; i1 = v; }
            else if (s > s2) { s2 = s; }
        }
        // warp top-2 merge (all lanes converge via full butterfly)
        #pragma unroll
        for (int off = 16; off > 0; off >>= 1) {
            const float os1 = __shfl_xor_sync(0xffffffffu, s1, off);
            const int   oi1 = __shfl_xor_sync(0xffffffffu, i1, off);
            const float os2 = __shfl_xor_sync(0xffffffffu, s2, off);
            if (os1 > s1 || (os1 == s1 && oi1 < i1)) {
                s2 = fmaxf(s1, os2); s1 = os1; i1 = oi1;
            } else {
                s2 = fmaxf(os1, s2);
            }
        }
        int best_i = i1;
        if (s1 - s2 < 1e-2f) {   // warp-uniform; ~1% of rows take the exact path
            float bs = -3.4e38f;
            int bi = 0;
            #pragma unroll
            for (int j = 0; j < 10; j++) {
                const int v = lane + (j << 5);
                const float u = urow[v];
                const float noise = -log_acc(-log_acc(u + 1e-10f) + 1e-10f);
                const float s = l[j] + noise;
                if (s > bs) { bs = s; bi = v; }
            }
            #pragma unroll
            for (int off = 16; off > 0; off >>= 1) {
                const float os = __shfl_xor_sync(0xffffffffu, bs, off);
                const int   oi = __shfl_xor_sync(0xffffffffu, bi, off);
                if (os > bs || (os == bs && oi < bi)) { bs = os; bi = oi; }
            }
            best_i = bi;
        }

        // noise-free softmax for avg_probs (loose tolerance)
        float lm = l[0];
        #pragma unroll
        for (int j = 1; j < 10; j++) lm = fmaxf(lm, l[j]);
        #pragma unroll
        for (int off = 16; off > 0; off >>= 1)
            lm = fmaxf(lm, __shfl_xor_sync(0xffffffffu, lm, off));
        float e[10];
        float sum = 0.0f;
        #pragma unroll
        for (int j = 0; j < 10; j++) { e[j] = __expf(l[j] - lm); sum += e[j]; }
        #pragma unroll
        for (int off = 16; off > 0; off >>= 1)
            sum += __shfl_xor_sync(0xffffffffu, sum, off);
        const float inv = 1.0f / sum;
        #pragma unroll
        for (int j = 0; j < 10; j++) acc[j] += e[j] * inv;

        const float4* srcv = (const float4*)(codevec + (size_t)(g * V_VARS + best_i) * D_CODE);
        float4* dstv = (float4*)(out + (size_t)n * 256 + g * D_CODE);
        dstv[lane] = srcv[lane];
    }

    #pragma unroll
    for (int j = 0; j < 10; j++)
        atomicAdd(&s_avg[g * V_VARS + lane + (j << 5)], acc[j]);
    __syncthreads();
    for (int i = tid; i < N_TOTAL; i += 256) atomicAdd(&g_avg[i], s_avg[i]);
}

// ---------------------------------------------------------------------------
__global__ void phase3_kernel(float* __restrict__ dst) {
    __shared__ float hsum[2];
    const int t = threadIdx.x;  // 640
    if (t < 2) hsum[t] = 0.0f;
    __syncthreads();
    const float a = g_avg[t] * (1.0f / 32768.0f);
    float ev = a * log_acc(a + 1e-7f);
    #pragma unroll
    for (int off = 16; off > 0; off >>= 1)
        ev += __shfl_xor_sync(0xffffffffu, ev, off);
    if ((t & 31) == 0) atomicAdd(&hsum[t / 320], ev);
    __syncthreads();
    if (t == 0) dst[0] = expf(-hsum[0]) + expf(-hsum[1]);
}

// ---------------------------------------------------------------------------
extern "C" void kernel_launch(void* const* d_in, const int* in_sizes, int n_in,
                              void* d_out, int out_size) {
    (void)in_sizes; (void)n_in;
    const float* hidden  = (const float*)d_in[0];  // [8,4096,512]
    const float* gumbel  = (const float*)d_in[1];  // [65536,320]
    const float* wproj   = (const float*)d_in[2];  // [512,640]
    const float* bias    = (const float*)d_in[3];  // [640]
    const float* codevec = (const float*)d_in[4];  // [640,128]
    float* out = (float*)d_out;

    cudaFuncSetAttribute(gemm_mma_kernel,
                         cudaFuncAttributeMaxDynamicSharedMemorySize, SMEM_GEMM);

    split_a_kernel<<<8192, 256>>>(hidden);
    split_b_kernel<<<640, 512>>>(wproj);
    gemm_mma_kernel<<<1280, 256, SMEM_GEMM>>>(bias);
    phase2_kernel<<<2048, 256>>>(gumbel, codevec, out);
    phase3_kernel<<<1, 640>>>(out + (out_size - 1));
}